// round 3
// baseline (speedup 1.0000x reference)
#include <cuda_runtime.h>
#include <math.h>

#define BB   8
#define CC   256
#define HH   64
#define WWW  64
#define NPIX 4096
#define NGRP 16
#define SCALE 0.0625f   /* 256^-0.5 */

/* ---- scratch (static device globals: allocation-free) ---- */
__device__ float g_qkv[(size_t)BB * 3 * CC * NPIX];   /* ~100.7 MB */
__device__ float g_y[2][BB * CC * 64];                /* means: [0]=mean over w (per h), [1]=mean over h (per w) */
__device__ float g_s[2][BB * CC * 64];                /* gate outputs x_h, x_w */

/* ================= 1. row/col means ================= */
__global__ void __launch_bounds__(256) means_kernel(const float* __restrict__ x) {
    __shared__ float tile[64][65];
    int bc = blockIdx.x;                 /* 0..B*C-1 */
    const float* xp = x + (size_t)bc * NPIX;
    int tid = threadIdx.x;
    #pragma unroll
    for (int t = 0; t < 16; t++) {
        int idx = tid + t * 256;
        tile[idx >> 6][idx & 63] = xp[idx];
    }
    __syncthreads();
    if (tid < 64) {
        float s = 0.f;
        #pragma unroll
        for (int w = 0; w < 64; w++) s += tile[tid][w];
        g_y[0][(size_t)bc * 64 + tid] = s * (1.0f / 64.0f);
    } else if (tid < 128) {
        int w = tid - 64;
        float s = 0.f;
        #pragma unroll
        for (int h = 0; h < 64; h++) s += tile[h][w];
        g_y[1][(size_t)bc * 64 + w] = s * (1.0f / 64.0f);
    }
}

/* ================= 2. GN + sigmoid branch =================
   grid: 16 = branch*8 + b ; block 256 (thread = output channel d) */
__global__ void __launch_bounds__(256) gn_kernel(const float* __restrict__ w1,
                                                 const float* __restrict__ b1,
                                                 const float* __restrict__ gamma,
                                                 const float* __restrict__ beta) {
    extern __shared__ float sm[];
    float* ys  = sm;            /* 256*64 */
    float* red = sm + 256 * 64; /* 512    */
    __shared__ float mu_s[NGRP], rs_s[NGRP];

    int br = blockIdx.x >> 3;
    int b  = blockIdx.x & 7;
    const float* y = g_y[br] + (size_t)b * CC * 64;
    int tid = threadIdx.x;

    #pragma unroll
    for (int t = 0; t < 16; t++) {
        int i4 = tid + t * 256;
        ((float4*)ys)[i4] = ((const float4*)y)[i4];
    }
    __syncthreads();

    float acc[64];
    #pragma unroll
    for (int l = 0; l < 64; l++) acc[l] = 0.f;

    const float* w1r = w1 + (size_t)tid * CC;
    for (int c = 0; c < CC; c++) {
        float wv = w1r[c];
        const float4* yr = (const float4*)(ys + c * 64);
        #pragma unroll
        for (int l4 = 0; l4 < 16; l4++) {
            float4 yv = yr[l4];
            acc[l4 * 4 + 0] += wv * yv.x;
            acc[l4 * 4 + 1] += wv * yv.y;
            acc[l4 * 4 + 2] += wv * yv.z;
            acc[l4 * 4 + 3] += wv * yv.w;
        }
    }
    float bias = b1[tid];
    float s1 = 0.f, s2 = 0.f;
    #pragma unroll
    for (int l = 0; l < 64; l++) {
        acc[l] += bias;
        s1 += acc[l];
        s2 += acc[l] * acc[l];
    }
    red[tid]       = s1;
    red[256 + tid] = s2;
    __syncthreads();
    if (tid < NGRP) {
        float S = 0.f, S2 = 0.f;
        #pragma unroll
        for (int k = 0; k < 16; k++) {
            S  += red[tid * 16 + k];
            S2 += red[256 + tid * 16 + k];
        }
        float mu  = S * (1.0f / 1024.0f);
        float var = S2 * (1.0f / 1024.0f) - mu * mu;
        mu_s[tid] = mu;
        rs_s[tid] = rsqrtf(var + 1e-5f);
    }
    __syncthreads();
    float mu = mu_s[tid >> 4], rs = rs_s[tid >> 4];
    float ga = gamma[tid], be = beta[tid];
    float* o = g_s[br] + ((size_t)b * CC + tid) * 64;
    #pragma unroll
    for (int l = 0; l < 64; l++) {
        float zn = (acc[l] - mu) * rs;
        float v  = zn * ga + be;
        o[l] = 1.0f / (1.0f + __expf(-v));
    }
}

/* ================= 3. QKV projection (tiled fp32 GEMM) =================
   grid (12, 64, 8), block 256; C_tile = 64x64, K-chunks of 32 */
__global__ void __launch_bounds__(256) qkv_kernel(const float* __restrict__ x,
                                                  const float* __restrict__ wq) {
    __shared__ float a_s[64][33];
    __shared__ float b_s[32][64];
    int mt = blockIdx.x, nt = blockIdx.y, b = blockIdx.z;
    const float* X = x + (size_t)b * CC * NPIX;
    float* outp = g_qkv + (size_t)b * 3 * CC * NPIX;
    int tid = threadIdx.x;
    int tx = tid & 15, ty = tid >> 4;
    int m0 = mt * 64, n0 = nt * 64;
    float acc[4][4];
    #pragma unroll
    for (int e = 0; e < 4; e++)
        #pragma unroll
        for (int f = 0; f < 4; f++) acc[e][f] = 0.f;

    for (int k0 = 0; k0 < CC; k0 += 32) {
        int cA = tid & 31, rA = tid >> 5;
        #pragma unroll
        for (int i = 0; i < 8; i++)
            a_s[rA + i * 8][cA] = wq[(size_t)(m0 + rA + i * 8) * CC + k0 + cA];
        #pragma unroll
        for (int i = 0; i < 2; i++) {
            int idx4 = tid + i * 256;
            int kk = idx4 >> 4, nn4 = idx4 & 15;
            *(float4*)&b_s[kk][nn4 * 4] =
                *(const float4*)(X + (size_t)(k0 + kk) * NPIX + n0 + nn4 * 4);
        }
        __syncthreads();
        #pragma unroll
        for (int kk = 0; kk < 32; kk++) {
            float4 bv = *(const float4*)&b_s[kk][tx * 4];
            float av[4];
            #pragma unroll
            for (int e = 0; e < 4; e++) av[e] = a_s[ty * 4 + e][kk];
            #pragma unroll
            for (int e = 0; e < 4; e++) {
                acc[e][0] += av[e] * bv.x;
                acc[e][1] += av[e] * bv.y;
                acc[e][2] += av[e] * bv.z;
                acc[e][3] += av[e] * bv.w;
            }
        }
        __syncthreads();
    }
    #pragma unroll
    for (int e = 0; e < 4; e++) {
        float4 v = make_float4(acc[e][0], acc[e][1], acc[e][2], acc[e][3]);
        *(float4*)(outp + (size_t)(m0 + ty * 4 + e) * NPIX + n0 + tx * 4) = v;
    }
}

/* ================= 4. flash attention + fused ELA =================
   grid (64, 8) = (query tile, batch); block 256; BM=BN=64, D=256 */
#define VP 66   /* V smem pitch */
#define PP 65   /* P smem pitch */
#define ATT_SMEM ((256*64 + 256*64 + 256*VP + 64*PP) * 4)

__global__ void __launch_bounds__(256) flash_kernel(const float* __restrict__ x,
                                                    float* __restrict__ out) {
    extern __shared__ float sm[];
    float* Qs = sm;                 /* [256][64]  */
    float* Ks = Qs + 256 * 64;      /* [256][64]  */
    float* Vs = Ks + 256 * 64;      /* [256][VP]  */
    float* Ps = Vs + 256 * VP;      /* [64][PP]   */

    int qt = blockIdx.x, b = blockIdx.y;
    int n0 = qt * 64;
    const float* qg = g_qkv + (size_t)b * 3 * CC * NPIX;
    const float* kg = qg + (size_t)CC * NPIX;
    const float* vg = kg + (size_t)CC * NPIX;

    int tid = threadIdx.x;
    int tx = tid & 15, ty = tid >> 4;

    /* load Q tile: Qs[c][i] */
    #pragma unroll
    for (int t = 0; t < 16; t++) {
        int idx4 = tid + t * 256;
        int c = idx4 >> 4, i4 = idx4 & 15;
        ((float4*)Qs)[idx4] = *(const float4*)(qg + (size_t)c * NPIX + n0 + i4 * 4);
    }

    float Ob[4][16];
    #pragma unroll
    for (int e = 0; e < 4; e++)
        #pragma unroll
        for (int cc = 0; cc < 16; cc++) Ob[e][cc] = 0.f;
    float mst[4], lst[4];
    #pragma unroll
    for (int e = 0; e < 4; e++) { mst[e] = -INFINITY; lst[e] = 0.f; }

    for (int kt = 0; kt < 64; kt++) {
        int m0 = kt * 64;
        __syncthreads();   /* previous O-phase done before K/V/P overwrite */

        #pragma unroll
        for (int t = 0; t < 16; t++) {
            int idx4 = tid + t * 256;
            int c = idx4 >> 4, i4 = idx4 & 15;
            ((float4*)Ks)[idx4] = *(const float4*)(kg + (size_t)c * NPIX + m0 + i4 * 4);
            float4 vv = *(const float4*)(vg + (size_t)c * NPIX + m0 + i4 * 4);
            float* vd = Vs + c * VP + i4 * 4;
            vd[0] = vv.x; vd[1] = vv.y; vd[2] = vv.z; vd[3] = vv.w;
        }
        __syncthreads();

        /* ---- S = scale * Q^T K (micro 4x4) ---- */
        float acc[4][4];
        #pragma unroll
        for (int e = 0; e < 4; e++)
            #pragma unroll
            for (int f = 0; f < 4; f++) acc[e][f] = 0.f;
        #pragma unroll 4
        for (int c = 0; c < 256; c++) {
            float4 qv = *(const float4*)(Qs + c * 64 + ty * 4);
            float4 kv = *(const float4*)(Ks + c * 64 + tx * 4);
            acc[0][0] += qv.x * kv.x; acc[0][1] += qv.x * kv.y; acc[0][2] += qv.x * kv.z; acc[0][3] += qv.x * kv.w;
            acc[1][0] += qv.y * kv.x; acc[1][1] += qv.y * kv.y; acc[1][2] += qv.y * kv.z; acc[1][3] += qv.y * kv.w;
            acc[2][0] += qv.z * kv.x; acc[2][1] += qv.z * kv.y; acc[2][2] += qv.z * kv.z; acc[2][3] += qv.z * kv.w;
            acc[3][0] += qv.w * kv.x; acc[3][1] += qv.w * kv.y; acc[3][2] += qv.w * kv.z; acc[3][3] += qv.w * kv.w;
        }
        #pragma unroll
        for (int e = 0; e < 4; e++)
            #pragma unroll
            for (int f = 0; f < 4; f++) acc[e][f] *= SCALE;

        /* ---- online softmax (row group = same ty across 16 tx lanes) ---- */
        float alpha[4];
        #pragma unroll
        for (int e = 0; e < 4; e++) {
            float mx = fmaxf(fmaxf(acc[e][0], acc[e][1]), fmaxf(acc[e][2], acc[e][3]));
            #pragma unroll
            for (int s = 8; s >= 1; s >>= 1)
                mx = fmaxf(mx, __shfl_xor_sync(0xffffffffu, mx, s));
            float mnew = fmaxf(mst[e], mx);
            alpha[e] = __expf(mst[e] - mnew);
            float rs = 0.f;
            #pragma unroll
            for (int f = 0; f < 4; f++) {
                float p = __expf(acc[e][f] - mnew);
                acc[e][f] = p;
                rs += p;
            }
            #pragma unroll
            for (int s = 8; s >= 1; s >>= 1)
                rs += __shfl_xor_sync(0xffffffffu, rs, s);
            lst[e] = lst[e] * alpha[e] + rs;
            mst[e] = mnew;
        }
        /* store P transposed: Ps[j][i] */
        #pragma unroll
        for (int e = 0; e < 4; e++)
            #pragma unroll
            for (int f = 0; f < 4; f++)
                Ps[(tx * 4 + f) * PP + ty * 4 + e] = acc[e][f];
        __syncthreads();

        /* ---- O accumulate: rows i=ty*4+e, dims c=tx+cc*16 ---- */
        #pragma unroll
        for (int e = 0; e < 4; e++)
            #pragma unroll
            for (int cc = 0; cc < 16; cc++) Ob[e][cc] *= alpha[e];

        #pragma unroll 2
        for (int j = 0; j < 64; j++) {
            float pv[4];
            #pragma unroll
            for (int e = 0; e < 4; e++) pv[e] = Ps[j * PP + ty * 4 + e];
            #pragma unroll
            for (int cc = 0; cc < 16; cc++) {
                float v = Vs[(tx + cc * 16) * VP + j];
                #pragma unroll
                for (int e = 0; e < 4; e++) Ob[e][cc] += pv[e] * v;
            }
        }
    }

    /* ---- epilogue: /l, + ELA, store ---- */
    float inv[4];
    #pragma unroll
    for (int e = 0; e < 4; e++) inv[e] = 1.0f / lst[e];
    const float* xg = x + (size_t)b * CC * NPIX;
    float* og = out + (size_t)b * CC * NPIX;
    int hh = qt;
    #pragma unroll
    for (int cc = 0; cc < 16; cc++) {
        int c = tx + cc * 16;
        float xhv = g_s[0][((size_t)b * CC + c) * 64 + hh];
        const float* xwp = &g_s[1][((size_t)b * CC + c) * 64];
        #pragma unroll
        for (int e = 0; e < 4; e++) {
            int i = ty * 4 + e;              /* ww = i, n = n0 + i */
            size_t gi = (size_t)c * NPIX + n0 + i;
            float ela = xg[gi] * xhv * xwp[i];
            og[gi] = Ob[e][cc] * inv[e] + ela;
        }
    }
}

/* ================= launch ================= */
extern "C" void kernel_launch(void* const* d_in, const int* in_sizes, int n_in,
                              void* d_out, int out_size) {
    const float* x     = (const float*)d_in[0];
    const float* wqkv  = (const float*)d_in[1];
    const float* w1    = (const float*)d_in[2];
    const float* b1    = (const float*)d_in[3];
    const float* gamma = (const float*)d_in[4];
    const float* beta  = (const float*)d_in[5];
    float* out = (float*)d_out;

    cudaFuncSetAttribute(gn_kernel, cudaFuncAttributeMaxDynamicSharedMemorySize,
                         (256 * 64 + 512) * 4);
    cudaFuncSetAttribute(flash_kernel, cudaFuncAttributeMaxDynamicSharedMemorySize,
                         ATT_SMEM);

    means_kernel<<<BB * CC, 256>>>(x);
    gn_kernel<<<16, 256, (256 * 64 + 512) * 4>>>(w1, b1, gamma, beta);
    qkv_kernel<<<dim3(12, 64, BB), 256>>>(x, wqkv);
    flash_kernel<<<dim3(64, BB), 256, ATT_SMEM>>>(x, out);
}

// round 4
// speedup vs baseline: 1.5644x; 1.5644x over previous
#include <cuda_runtime.h>
#include <math.h>
#include <stdint.h>

#define BB   8
#define CC   256
#define NPIX 4096
#define NGRP 16
#define SCALE 0.0625f   /* 256^-0.5 */

/* ---- scratch (static device globals: allocation-free) ---- */
__device__ float g_qkv[(size_t)BB * 3 * CC * NPIX];   /* ~100.7 MB */
__device__ float g_y[2][BB * CC * 64];
__device__ float g_s[2][BB * CC * 64];

/* ================= 1. row/col means ================= */
__global__ void __launch_bounds__(256) means_kernel(const float* __restrict__ x) {
    __shared__ float tile[64][65];
    int bc = blockIdx.x;
    const float* xp = x + (size_t)bc * NPIX;
    int tid = threadIdx.x;
    #pragma unroll
    for (int t = 0; t < 16; t++) {
        int idx = tid + t * 256;
        tile[idx >> 6][idx & 63] = xp[idx];
    }
    __syncthreads();
    if (tid < 64) {
        float s = 0.f;
        #pragma unroll
        for (int w = 0; w < 64; w++) s += tile[tid][w];
        g_y[0][(size_t)bc * 64 + tid] = s * (1.0f / 64.0f);
    } else if (tid < 128) {
        int w = tid - 64;
        float s = 0.f;
        #pragma unroll
        for (int h = 0; h < 64; h++) s += tile[h][w];
        g_y[1][(size_t)bc * 64 + w] = s * (1.0f / 64.0f);
    }
}

/* ================= 2. GN + sigmoid branch ================= */
__global__ void __launch_bounds__(256) gn_kernel(const float* __restrict__ w1,
                                                 const float* __restrict__ b1,
                                                 const float* __restrict__ gamma,
                                                 const float* __restrict__ beta) {
    extern __shared__ float sm[];
    float* ys  = sm;
    float* red = sm + 256 * 64;
    __shared__ float mu_s[NGRP], rs_s[NGRP];

    int br = blockIdx.x >> 3;
    int b  = blockIdx.x & 7;
    const float* y = g_y[br] + (size_t)b * CC * 64;
    int tid = threadIdx.x;

    #pragma unroll
    for (int t = 0; t < 16; t++) {
        int i4 = tid + t * 256;
        ((float4*)ys)[i4] = ((const float4*)y)[i4];
    }
    __syncthreads();

    float acc[64];
    #pragma unroll
    for (int l = 0; l < 64; l++) acc[l] = 0.f;

    const float* w1r = w1 + (size_t)tid * CC;
    for (int c = 0; c < CC; c++) {
        float wv = w1r[c];
        const float4* yr = (const float4*)(ys + c * 64);
        #pragma unroll
        for (int l4 = 0; l4 < 16; l4++) {
            float4 yv = yr[l4];
            acc[l4 * 4 + 0] += wv * yv.x;
            acc[l4 * 4 + 1] += wv * yv.y;
            acc[l4 * 4 + 2] += wv * yv.z;
            acc[l4 * 4 + 3] += wv * yv.w;
        }
    }
    float bias = b1[tid];
    float s1 = 0.f, s2 = 0.f;
    #pragma unroll
    for (int l = 0; l < 64; l++) {
        acc[l] += bias;
        s1 += acc[l];
        s2 += acc[l] * acc[l];
    }
    red[tid]       = s1;
    red[256 + tid] = s2;
    __syncthreads();
    if (tid < NGRP) {
        float S = 0.f, S2 = 0.f;
        #pragma unroll
        for (int k = 0; k < 16; k++) {
            S  += red[tid * 16 + k];
            S2 += red[256 + tid * 16 + k];
        }
        float mu  = S * (1.0f / 1024.0f);
        float var = S2 * (1.0f / 1024.0f) - mu * mu;
        mu_s[tid] = mu;
        rs_s[tid] = rsqrtf(var + 1e-5f);
    }
    __syncthreads();
    float mu = mu_s[tid >> 4], rs = rs_s[tid >> 4];
    float ga = gamma[tid], be = beta[tid];
    float* o = g_s[br] + ((size_t)b * CC + tid) * 64;
    #pragma unroll
    for (int l = 0; l < 64; l++) {
        float zn = (acc[l] - mu) * rs;
        float v  = zn * ga + be;
        o[l] = 1.0f / (1.0f + __expf(-v));
    }
}

/* ================= 3. QKV projection (tiled fp32 GEMM) ================= */
__global__ void __launch_bounds__(256) qkv_kernel(const float* __restrict__ x,
                                                  const float* __restrict__ wq) {
    __shared__ float a_s[64][33];
    __shared__ float b_s[32][64];
    int mt = blockIdx.x, nt = blockIdx.y, b = blockIdx.z;
    const float* X = x + (size_t)b * CC * NPIX;
    float* outp = g_qkv + (size_t)b * 3 * CC * NPIX;
    int tid = threadIdx.x;
    int tx = tid & 15, ty = tid >> 4;
    int m0 = mt * 64, n0 = nt * 64;
    float acc[4][4];
    #pragma unroll
    for (int e = 0; e < 4; e++)
        #pragma unroll
        for (int f = 0; f < 4; f++) acc[e][f] = 0.f;

    for (int k0 = 0; k0 < CC; k0 += 32) {
        int cA = tid & 31, rA = tid >> 5;
        #pragma unroll
        for (int i = 0; i < 8; i++)
            a_s[rA + i * 8][cA] = wq[(size_t)(m0 + rA + i * 8) * CC + k0 + cA];
        #pragma unroll
        for (int i = 0; i < 2; i++) {
            int idx4 = tid + i * 256;
            int kk = idx4 >> 4, nn4 = idx4 & 15;
            *(float4*)&b_s[kk][nn4 * 4] =
                *(const float4*)(X + (size_t)(k0 + kk) * NPIX + n0 + nn4 * 4);
        }
        __syncthreads();
        #pragma unroll
        for (int kk = 0; kk < 32; kk++) {
            float4 bv = *(const float4*)&b_s[kk][tx * 4];
            float av[4];
            #pragma unroll
            for (int e = 0; e < 4; e++) av[e] = a_s[ty * 4 + e][kk];
            #pragma unroll
            for (int e = 0; e < 4; e++) {
                acc[e][0] += av[e] * bv.x;
                acc[e][1] += av[e] * bv.y;
                acc[e][2] += av[e] * bv.z;
                acc[e][3] += av[e] * bv.w;
            }
        }
        __syncthreads();
    }
    #pragma unroll
    for (int e = 0; e < 4; e++) {
        float4 v = make_float4(acc[e][0], acc[e][1], acc[e][2], acc[e][3]);
        *(float4*)(outp + (size_t)(m0 + ty * 4 + e) * NPIX + n0 + tx * 4) = v;
    }
}

/* ================= 4. flash attention (tf32 mma.sync) + fused ELA =================
   grid (64, 8); block 256 = 8 warps.
   S warp tiling: (m = wid&3)*16 rows x (n = wid>>2)*32 cols
   PV warp tiling: same 16 rows x (wid>>2)*128 d-cols
   smem pitches chosen for conflict-free fragment LDS:
     Ks pitch 72 (banks t*8+g), Vs/Ps pitch 68 (banks g*4+t), Qs pitch 66 (2-way, small traffic) */
#define QP 66
#define KP 72
#define VP2 68
#define PP2 68
#define SM_QS  0
#define SM_KS  (SM_QS + 256 * QP)            /* 16896 */
#define SM_VS  (SM_KS + 256 * KP)            /* 35328 */
#define SM_PS  (SM_VS + 256 * VP2)           /* 52736 */
#define SM_MR  (SM_PS + 64 * PP2)            /* 57088 */
#define SM_LR  (SM_MR + 64)
#define SM_MP  (SM_LR + 64)                  /* [2][64] */
#define SM_SP  (SM_MP + 128)                 /* [2][64] */
#define ATT_SMEM ((SM_SP + 128) * 4)         /* 229888 B */

__device__ __forceinline__ uint32_t f2tf32(float x) {
    uint32_t r;
    asm("cvt.rna.tf32.f32 %0, %1;" : "=r"(r) : "f"(x));
    return r;
}

__device__ __forceinline__ void mma_tf32(float* d, const uint32_t* a,
                                         uint32_t b0, uint32_t b1) {
    asm volatile(
        "mma.sync.aligned.m16n8k8.row.col.f32.tf32.tf32.f32 "
        "{%0,%1,%2,%3}, {%4,%5,%6,%7}, {%8,%9}, {%0,%1,%2,%3};\n"
        : "+f"(d[0]), "+f"(d[1]), "+f"(d[2]), "+f"(d[3])
        : "r"(a[0]), "r"(a[1]), "r"(a[2]), "r"(a[3]), "r"(b0), "r"(b1));
}

__global__ void __launch_bounds__(256) flash_kernel(const float* __restrict__ x,
                                                    float* __restrict__ out) {
    extern __shared__ float sm[];
    float* Qs = sm + SM_QS;
    float* Ks = sm + SM_KS;
    float* Vs = sm + SM_VS;
    float* Ps = sm + SM_PS;
    float* mrow  = sm + SM_MR;
    float* lrow  = sm + SM_LR;
    float* mpart = sm + SM_MP;
    float* spart = sm + SM_SP;

    int qt = blockIdx.x, b = blockIdx.y;
    int n0 = qt * 64;
    const float* qg = g_qkv + (size_t)b * 3 * CC * NPIX;
    const float* kg = qg + (size_t)CC * NPIX;
    const float* vg = kg + (size_t)CC * NPIX;

    int tid  = threadIdx.x;
    int wid  = tid >> 5;
    int lane = tid & 31;
    int g = lane >> 2, t = lane & 3;
    int m0  = (wid & 3) * 16;
    int wn  = wid >> 2;
    int nn0 = wn * 32;
    int d0  = wn * 128;

    /* load Q tile: Qs[c][i], pitch QP (float2 stores, 8B aligned) */
    #pragma unroll
    for (int it = 0; it < 16; it++) {
        int idx4 = tid + it * 256;
        int c = idx4 >> 4, i4 = idx4 & 15;
        float4 qv = *(const float4*)(qg + (size_t)c * NPIX + n0 + i4 * 4);
        float* qd = Qs + c * QP + i4 * 4;
        ((float2*)qd)[0] = make_float2(qv.x, qv.y);
        ((float2*)qd)[1] = make_float2(qv.z, qv.w);
    }
    if (tid < 64) { mrow[tid] = -INFINITY; lrow[tid] = 0.f; }

    float o[16][4];
    #pragma unroll
    for (int nt = 0; nt < 16; nt++)
        #pragma unroll
        for (int e = 0; e < 4; e++) o[nt][e] = 0.f;

    int r0 = m0 + g, r1 = r0 + 8;

    for (int kt = 0; kt < 64; kt++) {
        int km0 = kt * 64;
        __syncthreads();                               /* sync_A */

        /* load K,V tiles: Ks[c][j] pitch KP, Vs[c][j] pitch VP2 (float4 ok) */
        #pragma unroll
        for (int it = 0; it < 16; it++) {
            int idx4 = tid + it * 256;
            int c = idx4 >> 4, j4 = idx4 & 15;
            *(float4*)(Ks + c * KP + j4 * 4) =
                *(const float4*)(kg + (size_t)c * NPIX + km0 + j4 * 4);
            *(float4*)(Vs + c * VP2 + j4 * 4) =
                *(const float4*)(vg + (size_t)c * NPIX + km0 + j4 * 4);
        }
        __syncthreads();                               /* sync_B */

        /* ---- S = Q^T K via tf32 mma (Q split hi/lo) ---- */
        float sacc[4][4];
        #pragma unroll
        for (int nt = 0; nt < 4; nt++)
            #pragma unroll
            for (int e = 0; e < 4; e++) sacc[nt][e] = 0.f;

        for (int k0 = 0; k0 < 256; k0 += 8) {
            const float* qa = Qs + (k0 + t) * QP + m0 + g;
            float av[4];
            av[0] = qa[0];
            av[1] = qa[8];
            av[2] = qa[4 * QP];
            av[3] = qa[4 * QP + 8];
            uint32_t ah[4], al[4];
            #pragma unroll
            for (int e = 0; e < 4; e++) {
                ah[e] = f2tf32(av[e]);
                al[e] = f2tf32(av[e] - __uint_as_float(ah[e]));
            }
            #pragma unroll
            for (int nt = 0; nt < 4; nt++) {
                const float* kb = Ks + (k0 + t) * KP + nn0 + nt * 8 + g;
                uint32_t b0 = f2tf32(kb[0]);
                uint32_t b1 = f2tf32(kb[4 * KP]);
                mma_tf32(sacc[nt], ah, b0, b1);
                mma_tf32(sacc[nt], al, b0, b1);
            }
        }

        /* ---- rowmax partials (raw logit units) ---- */
        float pm0 = -INFINITY, pm1 = -INFINITY;
        #pragma unroll
        for (int nt = 0; nt < 4; nt++) {
            pm0 = fmaxf(pm0, fmaxf(sacc[nt][0], sacc[nt][1]));
            pm1 = fmaxf(pm1, fmaxf(sacc[nt][2], sacc[nt][3]));
        }
        pm0 = fmaxf(pm0, __shfl_xor_sync(0xffffffffu, pm0, 1));
        pm0 = fmaxf(pm0, __shfl_xor_sync(0xffffffffu, pm0, 2));
        pm1 = fmaxf(pm1, __shfl_xor_sync(0xffffffffu, pm1, 1));
        pm1 = fmaxf(pm1, __shfl_xor_sync(0xffffffffu, pm1, 2));
        if (t == 0) { mpart[wn * 64 + r0] = pm0; mpart[wn * 64 + r1] = pm1; }
        __syncthreads();                               /* sync_C */

        float mo0 = mrow[r0], mo1 = mrow[r1];
        float mn0 = fmaxf(mo0, fmaxf(mpart[r0], mpart[64 + r0]));
        float mn1 = fmaxf(mo1, fmaxf(mpart[r1], mpart[64 + r1]));
        float alpha0 = __expf(SCALE * (mo0 - mn0));
        float alpha1 = __expf(SCALE * (mo1 - mn1));

        float ps0 = 0.f, ps1 = 0.f;
        #pragma unroll
        for (int nt = 0; nt < 4; nt++) {
            int col = nn0 + nt * 8 + 2 * t;
            float p0 = __expf(SCALE * (sacc[nt][0] - mn0));
            float p1 = __expf(SCALE * (sacc[nt][1] - mn0));
            float p2 = __expf(SCALE * (sacc[nt][2] - mn1));
            float p3 = __expf(SCALE * (sacc[nt][3] - mn1));
            Ps[r0 * PP2 + col]     = p0;
            Ps[r0 * PP2 + col + 1] = p1;
            Ps[r1 * PP2 + col]     = p2;
            Ps[r1 * PP2 + col + 1] = p3;
            ps0 += p0 + p1;
            ps1 += p2 + p3;
        }
        ps0 += __shfl_xor_sync(0xffffffffu, ps0, 1);
        ps0 += __shfl_xor_sync(0xffffffffu, ps0, 2);
        ps1 += __shfl_xor_sync(0xffffffffu, ps1, 1);
        ps1 += __shfl_xor_sync(0xffffffffu, ps1, 2);
        if (t == 0) { spart[wn * 64 + r0] = ps0; spart[wn * 64 + r1] = ps1; }
        __syncthreads();                               /* sync_D */

        if (wid == 0) {
            #pragma unroll
            for (int h = 0; h < 2; h++) {
                int rr = lane + h * 32;
                float mo = mrow[rr];
                float mn = fmaxf(mo, fmaxf(mpart[rr], mpart[64 + rr]));
                lrow[rr] = lrow[rr] * __expf(SCALE * (mo - mn))
                         + spart[rr] + spart[64 + rr];
                mrow[rr] = mn;
            }
        }

        /* ---- O rescale + PV mma ---- */
        #pragma unroll
        for (int nt = 0; nt < 16; nt++) {
            o[nt][0] *= alpha0; o[nt][1] *= alpha0;
            o[nt][2] *= alpha1; o[nt][3] *= alpha1;
        }
        #pragma unroll
        for (int ks = 0; ks < 8; ks++) {
            const float* pa = Ps + r0 * PP2 + ks * 8 + t;
            uint32_t ua[4];
            ua[0] = f2tf32(pa[0]);
            ua[1] = f2tf32(pa[8 * PP2]);
            ua[2] = f2tf32(pa[4]);
            ua[3] = f2tf32(pa[8 * PP2 + 4]);
            #pragma unroll
            for (int nt = 0; nt < 16; nt++) {
                const float* vb = Vs + (d0 + nt * 8 + g) * VP2 + ks * 8 + t;
                uint32_t b0 = f2tf32(vb[0]);
                uint32_t b1 = f2tf32(vb[4]);
                mma_tf32(o[nt], ua, b0, b1);
            }
        }
    }

    __syncthreads();
    float il0 = 1.0f / lrow[r0];
    float il1 = 1.0f / lrow[r1];

    /* epilogue: normalize, add ELA, store */
    const float* xg = x + (size_t)b * CC * NPIX;
    float* og = out + (size_t)b * CC * NPIX;
    int i0 = m0 + g, i1 = i0 + 8;     /* w coords; h = qt */
    #pragma unroll
    for (int nt = 0; nt < 16; nt++) {
        #pragma unroll
        for (int bc = 0; bc < 2; bc++) {
            int d = d0 + nt * 8 + 2 * t + bc;
            float xh  = g_s[0][((size_t)b * CC + d) * 64 + qt];
            float xw0 = g_s[1][((size_t)b * CC + d) * 64 + i0];
            float xw1 = g_s[1][((size_t)b * CC + d) * 64 + i1];
            size_t base = (size_t)d * NPIX + n0;
            og[base + i0] = o[nt][bc]     * il0 + xg[base + i0] * xh * xw0;
            og[base + i1] = o[nt][2 + bc] * il1 + xg[base + i1] * xh * xw1;
        }
    }
}

/* ================= launch ================= */
extern "C" void kernel_launch(void* const* d_in, const int* in_sizes, int n_in,
                              void* d_out, int out_size) {
    const float* x     = (const float*)d_in[0];
    const float* wqkv  = (const float*)d_in[1];
    const float* w1    = (const float*)d_in[2];
    const float* b1    = (const float*)d_in[3];
    const float* gamma = (const float*)d_in[4];
    const float* beta  = (const float*)d_in[5];
    float* out = (float*)d_out;

    cudaFuncSetAttribute(gn_kernel, cudaFuncAttributeMaxDynamicSharedMemorySize,
                         (256 * 64 + 512) * 4);
    cudaFuncSetAttribute(flash_kernel, cudaFuncAttributeMaxDynamicSharedMemorySize,
                         ATT_SMEM);

    means_kernel<<<BB * CC, 256>>>(x);
    gn_kernel<<<16, 256, (256 * 64 + 512) * 4>>>(w1, b1, gamma, beta);
    qkv_kernel<<<dim3(12, 64, BB), 256>>>(x, wqkv);
    flash_kernel<<<dim3(64, BB), 256, ATT_SMEM>>>(x, out);
}

// round 6
// speedup vs baseline: 1.6491x; 1.0541x over previous
#include <cuda_runtime.h>
#include <math.h>
#include <stdint.h>

#define BB   8
#define CC   256
#define NPIX 4096
#define NGRP 16
#define SCALE 0.0625f   /* 256^-0.5 */

/* ---- scratch (static device globals: allocation-free) ---- */
__device__ float g_qkv[(size_t)BB * 3 * CC * NPIX];
__device__ float g_y[2][BB * CC * 64];
__device__ float g_s[2][BB * CC * 64];

/* ================= 1. row/col means ================= */
__global__ void __launch_bounds__(256) means_kernel(const float* __restrict__ x) {
    __shared__ float tile[64][65];
    int bc = blockIdx.x;
    const float* xp = x + (size_t)bc * NPIX;
    int tid = threadIdx.x;
    #pragma unroll
    for (int t = 0; t < 16; t++) {
        int idx = tid + t * 256;
        tile[idx >> 6][idx & 63] = xp[idx];
    }
    __syncthreads();
    if (tid < 64) {
        float s = 0.f;
        #pragma unroll
        for (int w = 0; w < 64; w++) s += tile[tid][w];
        g_y[0][(size_t)bc * 64 + tid] = s * (1.0f / 64.0f);
    } else if (tid < 128) {
        int w = tid - 64;
        float s = 0.f;
        #pragma unroll
        for (int h = 0; h < 64; h++) s += tile[h][w];
        g_y[1][(size_t)bc * 64 + w] = s * (1.0f / 64.0f);
    }
}

/* ================= 2. GN + sigmoid branch ================= */
__global__ void __launch_bounds__(256) gn_kernel(const float* __restrict__ w1,
                                                 const float* __restrict__ b1,
                                                 const float* __restrict__ gamma,
                                                 const float* __restrict__ beta) {
    extern __shared__ float sm[];
    float* ys  = sm;
    float* red = sm + 256 * 64;
    __shared__ float mu_s[NGRP], rs_s[NGRP];

    int br = blockIdx.x >> 3;
    int b  = blockIdx.x & 7;
    const float* y = g_y[br] + (size_t)b * CC * 64;
    int tid = threadIdx.x;

    #pragma unroll
    for (int t = 0; t < 16; t++) {
        int i4 = tid + t * 256;
        ((float4*)ys)[i4] = ((const float4*)y)[i4];
    }
    __syncthreads();

    float acc[64];
    #pragma unroll
    for (int l = 0; l < 64; l++) acc[l] = 0.f;

    const float* w1r = w1 + (size_t)tid * CC;
    for (int c = 0; c < CC; c++) {
        float wv = w1r[c];
        const float4* yr = (const float4*)(ys + c * 64);
        #pragma unroll
        for (int l4 = 0; l4 < 16; l4++) {
            float4 yv = yr[l4];
            acc[l4 * 4 + 0] += wv * yv.x;
            acc[l4 * 4 + 1] += wv * yv.y;
            acc[l4 * 4 + 2] += wv * yv.z;
            acc[l4 * 4 + 3] += wv * yv.w;
        }
    }
    float bias = b1[tid];
    float s1 = 0.f, s2 = 0.f;
    #pragma unroll
    for (int l = 0; l < 64; l++) {
        acc[l] += bias;
        s1 += acc[l];
        s2 += acc[l] * acc[l];
    }
    red[tid]       = s1;
    red[256 + tid] = s2;
    __syncthreads();
    if (tid < NGRP) {
        float S = 0.f, S2 = 0.f;
        #pragma unroll
        for (int k = 0; k < 16; k++) {
            S  += red[tid * 16 + k];
            S2 += red[256 + tid * 16 + k];
        }
        float mu  = S * (1.0f / 1024.0f);
        float var = S2 * (1.0f / 1024.0f) - mu * mu;
        mu_s[tid] = mu;
        rs_s[tid] = rsqrtf(var + 1e-5f);
    }
    __syncthreads();
    float mu = mu_s[tid >> 4], rs = rs_s[tid >> 4];
    float ga = gamma[tid], be = beta[tid];
    float* o = g_s[br] + ((size_t)b * CC + tid) * 64;
    #pragma unroll
    for (int l = 0; l < 64; l++) {
        float zn = (acc[l] - mu) * rs;
        float v  = zn * ga + be;
        o[l] = 1.0f / (1.0f + __expf(-v));
    }
}

/* ================= 3. QKV projection (tiled fp32 GEMM) ================= */
__global__ void __launch_bounds__(256) qkv_kernel(const float* __restrict__ x,
                                                  const float* __restrict__ wq) {
    __shared__ float a_s[64][33];
    __shared__ float b_s[32][64];
    int mt = blockIdx.x, nt = blockIdx.y, b = blockIdx.z;
    const float* X = x + (size_t)b * CC * NPIX;
    float* outp = g_qkv + (size_t)b * 3 * CC * NPIX;
    int tid = threadIdx.x;
    int tx = tid & 15, ty = tid >> 4;
    int m0 = mt * 64, n0 = nt * 64;
    float acc[4][4];
    #pragma unroll
    for (int e = 0; e < 4; e++)
        #pragma unroll
        for (int f = 0; f < 4; f++) acc[e][f] = 0.f;

    for (int k0 = 0; k0 < CC; k0 += 32) {
        int cA = tid & 31, rA = tid >> 5;
        #pragma unroll
        for (int i = 0; i < 8; i++)
            a_s[rA + i * 8][cA] = wq[(size_t)(m0 + rA + i * 8) * CC + k0 + cA];
        #pragma unroll
        for (int i = 0; i < 2; i++) {
            int idx4 = tid + i * 256;
            int kk = idx4 >> 4, nn4 = idx4 & 15;
            *(float4*)&b_s[kk][nn4 * 4] =
                *(const float4*)(X + (size_t)(k0 + kk) * NPIX + n0 + nn4 * 4);
        }
        __syncthreads();
        #pragma unroll
        for (int kk = 0; kk < 32; kk++) {
            float4 bv = *(const float4*)&b_s[kk][tx * 4];
            float av[4];
            #pragma unroll
            for (int e = 0; e < 4; e++) av[e] = a_s[ty * 4 + e][kk];
            #pragma unroll
            for (int e = 0; e < 4; e++) {
                acc[e][0] += av[e] * bv.x;
                acc[e][1] += av[e] * bv.y;
                acc[e][2] += av[e] * bv.z;
                acc[e][3] += av[e] * bv.w;
            }
        }
        __syncthreads();
    }
    #pragma unroll
    for (int e = 0; e < 4; e++) {
        float4 v = make_float4(acc[e][0], acc[e][1], acc[e][2], acc[e][3]);
        *(float4*)(outp + (size_t)(m0 + ty * 4 + e) * NPIX + n0 + tx * 4) = v;
    }
}

/* ================= 4. flash attention (tf32 mma, pre-converted operands) ====
   grid (64, 8); block 512 = 16 warps.
   S:  warp grid 4(row)x4(col): each warp 16 rows x 16 cols
   PV: each warp 16 rows x 64 d-cols
   All tf32 conversions hoisted: Q once per block, K/V once per tile load,
   P once at Ps write. */
#define QP  66
#define KP  72
#define VPX 68
#define PPX 68
#define SM_QS  0
#define SM_KS  (SM_QS + 256 * QP)
#define SM_VS  (SM_KS + 256 * KP)
#define SM_PS  (SM_VS + 256 * VPX)
#define SM_MR  (SM_PS + 64 * PPX)
#define SM_LR  (SM_MR + 64)
#define SM_MP  (SM_LR + 64)              /* [4][64] */
#define SM_SP  (SM_MP + 256)             /* [4][64] */
#define ATT_SMEM ((SM_SP + 256) * 4)     /* 230,912 B */

__device__ __forceinline__ uint32_t f2tf32(float x) {
    uint32_t r;
    asm("cvt.rna.tf32.f32 %0, %1;" : "=r"(r) : "f"(x));
    return r;
}
__device__ __forceinline__ float tf32f(float x) {
    return __uint_as_float(f2tf32(x));
}

__device__ __forceinline__ void mma_tf32(float* d, const uint32_t* a,
                                         uint32_t b0, uint32_t b1) {
    asm volatile(
        "mma.sync.aligned.m16n8k8.row.col.f32.tf32.tf32.f32 "
        "{%0,%1,%2,%3}, {%4,%5,%6,%7}, {%8,%9}, {%0,%1,%2,%3};\n"
        : "+f"(d[0]), "+f"(d[1]), "+f"(d[2]), "+f"(d[3])
        : "r"(a[0]), "r"(a[1]), "r"(a[2]), "r"(a[3]), "r"(b0), "r"(b1));
}

__global__ void __launch_bounds__(512) flash_kernel(const float* __restrict__ x,
                                                    float* __restrict__ out) {
    extern __shared__ float sm[];
    float* Qs = sm + SM_QS;
    float* Ks = sm + SM_KS;
    float* Vs = sm + SM_VS;
    float* Ps = sm + SM_PS;
    float* mrow  = sm + SM_MR;
    float* lrow  = sm + SM_LR;
    float* mpart = sm + SM_MP;
    float* spart = sm + SM_SP;

    int qt = blockIdx.x, b = blockIdx.y;
    int n0 = qt * 64;
    const float* qg = g_qkv + (size_t)b * 3 * CC * NPIX;
    const float* kg = qg + (size_t)CC * NPIX;
    const float* vg = kg + (size_t)CC * NPIX;

    int tid  = threadIdx.x;
    int wid  = tid >> 5;
    int lane = tid & 31;
    int g = lane >> 2, t = lane & 3;
    int wr = wid & 3, wc = wid >> 2;
    int m0  = wr * 16;
    int nn0 = wc * 16;
    int d0  = wc * 64;

    /* load Q tile, convert to tf32 once: Qs[c][i], pitch QP */
    #pragma unroll
    for (int it = 0; it < 8; it++) {
        int idx4 = tid + it * 512;
        int c = idx4 >> 4, i4 = idx4 & 15;
        float4 qv = *(const float4*)(qg + (size_t)c * NPIX + n0 + i4 * 4);
        float* qd = Qs + c * QP + i4 * 4;
        qd[0] = tf32f(qv.x); qd[1] = tf32f(qv.y);
        qd[2] = tf32f(qv.z); qd[3] = tf32f(qv.w);
    }
    if (tid < 64) { mrow[tid] = -INFINITY; lrow[tid] = 0.f; }

    float o[8][4];
    #pragma unroll
    for (int nt = 0; nt < 8; nt++)
        #pragma unroll
        for (int e = 0; e < 4; e++) o[nt][e] = 0.f;

    int r0 = m0 + g, r1 = r0 + 8;

    for (int kt = 0; kt < 64; kt++) {
        int km0 = kt * 64;
        __syncthreads();                               /* prev PV done */

        /* load + convert K,V tiles */
        #pragma unroll
        for (int it = 0; it < 8; it++) {
            int idx4 = tid + it * 512;
            int c = idx4 >> 4, j4 = idx4 & 15;
            float4 kv = *(const float4*)(kg + (size_t)c * NPIX + km0 + j4 * 4);
            float* kd = Ks + c * KP + j4 * 4;
            kd[0] = tf32f(kv.x); kd[1] = tf32f(kv.y);
            kd[2] = tf32f(kv.z); kd[3] = tf32f(kv.w);
            float4 vv = *(const float4*)(vg + (size_t)c * NPIX + km0 + j4 * 4);
            float* vd = Vs + c * VPX + j4 * 4;
            vd[0] = tf32f(vv.x); vd[1] = tf32f(vv.y);
            vd[2] = tf32f(vv.z); vd[3] = tf32f(vv.w);
        }
        __syncthreads();                               /* tiles ready */

        /* ---- S = Q^T K via tf32 mma ---- */
        float sacc[2][4];
        #pragma unroll
        for (int nt = 0; nt < 2; nt++)
            #pragma unroll
            for (int e = 0; e < 4; e++) sacc[nt][e] = 0.f;

        #pragma unroll 4
        for (int k0 = 0; k0 < 256; k0 += 8) {
            const float* qa = Qs + (k0 + t) * QP + m0 + g;
            uint32_t a[4];
            a[0] = __float_as_uint(qa[0]);
            a[1] = __float_as_uint(qa[8]);
            a[2] = __float_as_uint(qa[4 * QP]);
            a[3] = __float_as_uint(qa[4 * QP + 8]);
            #pragma unroll
            for (int nt = 0; nt < 2; nt++) {
                const float* kb = Ks + (k0 + t) * KP + nn0 + nt * 8 + g;
                mma_tf32(sacc[nt], a, __float_as_uint(kb[0]),
                         __float_as_uint(kb[4 * KP]));
            }
        }

        /* ---- rowmax partials ---- */
        float pm0 = fmaxf(fmaxf(sacc[0][0], sacc[0][1]), fmaxf(sacc[1][0], sacc[1][1]));
        float pm1 = fmaxf(fmaxf(sacc[0][2], sacc[0][3]), fmaxf(sacc[1][2], sacc[1][3]));
        pm0 = fmaxf(pm0, __shfl_xor_sync(0xffffffffu, pm0, 1));
        pm0 = fmaxf(pm0, __shfl_xor_sync(0xffffffffu, pm0, 2));
        pm1 = fmaxf(pm1, __shfl_xor_sync(0xffffffffu, pm1, 1));
        pm1 = fmaxf(pm1, __shfl_xor_sync(0xffffffffu, pm1, 2));
        if (t == 0) { mpart[wc * 64 + r0] = pm0; mpart[wc * 64 + r1] = pm1; }
        __syncthreads();                               /* maxes ready */

        float mo0 = mrow[r0], mo1 = mrow[r1];
        float mn0 = fmaxf(fmaxf(mo0, fmaxf(mpart[r0], mpart[64 + r0])),
                          fmaxf(mpart[128 + r0], mpart[192 + r0]));
        float mn1 = fmaxf(fmaxf(mo1, fmaxf(mpart[r1], mpart[64 + r1])),
                          fmaxf(mpart[128 + r1], mpart[192 + r1]));
        float alpha0 = __expf(SCALE * (mo0 - mn0));
        float alpha1 = __expf(SCALE * (mo1 - mn1));

        float ps0, ps1;
        {
            int col = nn0 + 2 * t;
            float p00 = __expf(SCALE * (sacc[0][0] - mn0));
            float p01 = __expf(SCALE * (sacc[0][1] - mn0));
            float p02 = __expf(SCALE * (sacc[0][2] - mn1));
            float p03 = __expf(SCALE * (sacc[0][3] - mn1));
            float p10 = __expf(SCALE * (sacc[1][0] - mn0));
            float p11 = __expf(SCALE * (sacc[1][1] - mn0));
            float p12 = __expf(SCALE * (sacc[1][2] - mn1));
            float p13 = __expf(SCALE * (sacc[1][3] - mn1));
            *(float2*)(Ps + r0 * PPX + col)     = make_float2(tf32f(p00), tf32f(p01));
            *(float2*)(Ps + r1 * PPX + col)     = make_float2(tf32f(p02), tf32f(p03));
            *(float2*)(Ps + r0 * PPX + col + 8) = make_float2(tf32f(p10), tf32f(p11));
            *(float2*)(Ps + r1 * PPX + col + 8) = make_float2(tf32f(p12), tf32f(p13));
            ps0 = p00 + p01 + p10 + p11;
            ps1 = p02 + p03 + p12 + p13;
        }
        ps0 += __shfl_xor_sync(0xffffffffu, ps0, 1);
        ps0 += __shfl_xor_sync(0xffffffffu, ps0, 2);
        ps1 += __shfl_xor_sync(0xffffffffu, ps1, 1);
        ps1 += __shfl_xor_sync(0xffffffffu, ps1, 2);
        if (t == 0) { spart[wc * 64 + r0] = ps0; spart[wc * 64 + r1] = ps1; }
        __syncthreads();                               /* Ps + sums ready */

        if (wid == 0) {
            #pragma unroll
            for (int h = 0; h < 2; h++) {
                int rr = lane + h * 32;
                float mo = mrow[rr];
                float mn = fmaxf(fmaxf(mo, fmaxf(mpart[rr], mpart[64 + rr])),
                                 fmaxf(mpart[128 + rr], mpart[192 + rr]));
                lrow[rr] = lrow[rr] * __expf(SCALE * (mo - mn))
                         + spart[rr] + spart[64 + rr]
                         + spart[128 + rr] + spart[192 + rr];
                mrow[rr] = mn;
            }
        }

        /* ---- O rescale + PV mma ---- */
        #pragma unroll
        for (int nt = 0; nt < 8; nt++) {
            o[nt][0] *= alpha0; o[nt][1] *= alpha0;
            o[nt][2] *= alpha1; o[nt][3] *= alpha1;
        }
        #pragma unroll
        for (int ks = 0; ks < 8; ks++) {
            const float* pa = Ps + r0 * PPX + ks * 8 + t;
            uint32_t ua[4];
            ua[0] = __float_as_uint(pa[0]);
            ua[1] = __float_as_uint(pa[8 * PPX]);
            ua[2] = __float_as_uint(pa[4]);
            ua[3] = __float_as_uint(pa[8 * PPX + 4]);
            #pragma unroll
            for (int nt = 0; nt < 8; nt++) {
                const float* vb = Vs + (d0 + nt * 8 + g) * VPX + ks * 8 + t;
                mma_tf32(o[nt], ua, __float_as_uint(vb[0]),
                         __float_as_uint(vb[4]));
            }
        }
    }

    __syncthreads();
    float il0 = 1.0f / lrow[r0];
    float il1 = 1.0f / lrow[r1];

    /* epilogue: normalize, add ELA, store */
    const float* xg = x + (size_t)b * CC * NPIX;
    float* og = out + (size_t)b * CC * NPIX;
    int i0 = m0 + g, i1 = i0 + 8;     /* w coords; h = qt */
    #pragma unroll
    for (int nt = 0; nt < 8; nt++) {
        #pragma unroll
        for (int bc = 0; bc < 2; bc++) {
            int d = d0 + nt * 8 + 2 * t + bc;
            float xh  = g_s[0][((size_t)b * CC + d) * 64 + qt];
            float xw0 = g_s[1][((size_t)b * CC + d) * 64 + i0];
            float xw1 = g_s[1][((size_t)b * CC + d) * 64 + i1];
            size_t base = (size_t)d * NPIX + n0;
            og[base + i0] = o[nt][bc]     * il0 + xg[base + i0] * xh * xw0;
            og[base + i1] = o[nt][2 + bc] * il1 + xg[base + i1] * xh * xw1;
        }
    }
}

/* ================= launch ================= */
extern "C" void kernel_launch(void* const* d_in, const int* in_sizes, int n_in,
                              void* d_out, int out_size) {
    const float* x     = (const float*)d_in[0];
    const float* wqkv  = (const float*)d_in[1];
    const float* w1    = (const float*)d_in[2];
    const float* b1    = (const float*)d_in[3];
    const float* gamma = (const float*)d_in[4];
    const float* beta  = (const float*)d_in[5];
    float* out = (float*)d_out;

    cudaFuncSetAttribute(gn_kernel, cudaFuncAttributeMaxDynamicSharedMemorySize,
                         (256 * 64 + 512) * 4);
    cudaFuncSetAttribute(flash_kernel, cudaFuncAttributeMaxDynamicSharedMemorySize,
                         ATT_SMEM);

    means_kernel<<<BB * CC, 256>>>(x);
    gn_kernel<<<16, 256, (256 * 64 + 512) * 4>>>(w1, b1, gamma, beta);
    qkv_kernel<<<dim3(12, 64, BB), 256>>>(x, wqkv);
    flash_kernel<<<dim3(64, BB), 512, ATT_SMEM>>>(x, out);
}

// round 7
// speedup vs baseline: 2.8973x; 1.7569x over previous
#include <cuda_runtime.h>
#include <math.h>
#include <stdint.h>

#define BB   8
#define CC   256
#define NPIX 4096
#define NGRP 16
#define SCALE 0.0625f   /* 256^-0.5 */

/* ---- scratch (static device globals: allocation-free) ---- */
__device__ float g_qkv[(size_t)BB * 3 * CC * NPIX];
__device__ float g_y[2][BB * CC * 64];
__device__ float g_s[2][BB * CC * 64];

/* ================= 1. row/col means ================= */
__global__ void __launch_bounds__(256) means_kernel(const float* __restrict__ x) {
    __shared__ float tile[64][65];
    int bc = blockIdx.x;
    const float* xp = x + (size_t)bc * NPIX;
    int tid = threadIdx.x;
    #pragma unroll
    for (int t = 0; t < 16; t++) {
        int idx = tid + t * 256;
        tile[idx >> 6][idx & 63] = xp[idx];
    }
    __syncthreads();
    if (tid < 64) {
        float s = 0.f;
        #pragma unroll
        for (int w = 0; w < 64; w++) s += tile[tid][w];
        g_y[0][(size_t)bc * 64 + tid] = s * (1.0f / 64.0f);
    } else if (tid < 128) {
        int w = tid - 64;
        float s = 0.f;
        #pragma unroll
        for (int h = 0; h < 64; h++) s += tile[h][w];
        g_y[1][(size_t)bc * 64 + w] = s * (1.0f / 64.0f);
    }
}

/* ================= 2. GN + sigmoid branch ================= */
__global__ void __launch_bounds__(256) gn_kernel(const float* __restrict__ w1,
                                                 const float* __restrict__ b1,
                                                 const float* __restrict__ gamma,
                                                 const float* __restrict__ beta) {
    extern __shared__ float sm[];
    float* ys  = sm;
    float* red = sm + 256 * 64;
    __shared__ float mu_s[NGRP], rs_s[NGRP];

    int br = blockIdx.x >> 3;
    int b  = blockIdx.x & 7;
    const float* y = g_y[br] + (size_t)b * CC * 64;
    int tid = threadIdx.x;

    #pragma unroll
    for (int t = 0; t < 16; t++) {
        int i4 = tid + t * 256;
        ((float4*)ys)[i4] = ((const float4*)y)[i4];
    }
    __syncthreads();

    float acc[64];
    #pragma unroll
    for (int l = 0; l < 64; l++) acc[l] = 0.f;

    const float* w1r = w1 + (size_t)tid * CC;
    for (int c = 0; c < CC; c++) {
        float wv = w1r[c];
        const float4* yr = (const float4*)(ys + c * 64);
        #pragma unroll
        for (int l4 = 0; l4 < 16; l4++) {
            float4 yv = yr[l4];
            acc[l4 * 4 + 0] += wv * yv.x;
            acc[l4 * 4 + 1] += wv * yv.y;
            acc[l4 * 4 + 2] += wv * yv.z;
            acc[l4 * 4 + 3] += wv * yv.w;
        }
    }
    float bias = b1[tid];
    float s1 = 0.f, s2 = 0.f;
    #pragma unroll
    for (int l = 0; l < 64; l++) {
        acc[l] += bias;
        s1 += acc[l];
        s2 += acc[l] * acc[l];
    }
    red[tid]       = s1;
    red[256 + tid] = s2;
    __syncthreads();
    if (tid < NGRP) {
        float S = 0.f, S2 = 0.f;
        #pragma unroll
        for (int k = 0; k < 16; k++) {
            S  += red[tid * 16 + k];
            S2 += red[256 + tid * 16 + k];
        }
        float mu  = S * (1.0f / 1024.0f);
        float var = S2 * (1.0f / 1024.0f) - mu * mu;
        mu_s[tid] = mu;
        rs_s[tid] = rsqrtf(var + 1e-5f);
    }
    __syncthreads();
    float mu = mu_s[tid >> 4], rs = rs_s[tid >> 4];
    float ga = gamma[tid], be = beta[tid];
    float* o = g_s[br] + ((size_t)b * CC + tid) * 64;
    #pragma unroll
    for (int l = 0; l < 64; l++) {
        float zn = (acc[l] - mu) * rs;
        float v  = zn * ga + be;
        o[l] = 1.0f / (1.0f + __expf(-v));
    }
}

/* ================= 3. QKV projection (tiled fp32 GEMM) ================= */
__global__ void __launch_bounds__(256) qkv_kernel(const float* __restrict__ x,
                                                  const float* __restrict__ wq) {
    __shared__ float a_s[64][33];
    __shared__ float b_s[32][64];
    int mt = blockIdx.x, nt = blockIdx.y, b = blockIdx.z;
    const float* X = x + (size_t)b * CC * NPIX;
    float* outp = g_qkv + (size_t)b * 3 * CC * NPIX;
    int tid = threadIdx.x;
    int tx = tid & 15, ty = tid >> 4;
    int m0 = mt * 64, n0 = nt * 64;
    float acc[4][4];
    #pragma unroll
    for (int e = 0; e < 4; e++)
        #pragma unroll
        for (int f = 0; f < 4; f++) acc[e][f] = 0.f;

    for (int k0 = 0; k0 < CC; k0 += 32) {
        int cA = tid & 31, rA = tid >> 5;
        #pragma unroll
        for (int i = 0; i < 8; i++)
            a_s[rA + i * 8][cA] = wq[(size_t)(m0 + rA + i * 8) * CC + k0 + cA];
        #pragma unroll
        for (int i = 0; i < 2; i++) {
            int idx4 = tid + i * 256;
            int kk = idx4 >> 4, nn4 = idx4 & 15;
            *(float4*)&b_s[kk][nn4 * 4] =
                *(const float4*)(X + (size_t)(k0 + kk) * NPIX + n0 + nn4 * 4);
        }
        __syncthreads();
        #pragma unroll
        for (int kk = 0; kk < 32; kk++) {
            float4 bv = *(const float4*)&b_s[kk][tx * 4];
            float av[4];
            #pragma unroll
            for (int e = 0; e < 4; e++) av[e] = a_s[ty * 4 + e][kk];
            #pragma unroll
            for (int e = 0; e < 4; e++) {
                acc[e][0] += av[e] * bv.x;
                acc[e][1] += av[e] * bv.y;
                acc[e][2] += av[e] * bv.z;
                acc[e][3] += av[e] * bv.w;
            }
        }
        __syncthreads();
    }
    #pragma unroll
    for (int e = 0; e < 4; e++) {
        float4 v = make_float4(acc[e][0], acc[e][1], acc[e][2], acc[e][3]);
        *(float4*)(outp + (size_t)(m0 + ty * 4 + e) * NPIX + n0 + tx * 4) = v;
    }
}

/* ================= 4. flash attention (tf32 mma + cp.async pipeline) =======
   grid (64, 8); block 512 = 16 warps, warp grid 4x4.
   - Q pre-packed in fragment order (1 LDS.128 per A-frag)
   - K/V loaded raw via cp.async; HW truncates fp32->tf32 in the MMA
   - P truncated once at Ps write (numerator/denominator consistent)
   - overlap: V(kt) load || S-phase;  K(kt+1) load || softmax+PV */
#define KP  72
#define VPX 68
#define PPX 68
#define QFS (32 * 4 * 32 * 4)            /* 16384 floats, frag-packed Q */
#define SM_QF  0
#define SM_KS  (SM_QF + QFS)
#define SM_VS  (SM_KS + 256 * KP)
#define SM_PS  (SM_VS + 256 * VPX)
#define SM_MR  (SM_PS + 64 * PPX)
#define SM_LR  (SM_MR + 64)
#define SM_MP  (SM_LR + 64)              /* [4][64] */
#define SM_SP  (SM_MP + 256)             /* [4][64] */
#define ATT_SMEM ((SM_SP + 256) * 4)     /* 228,864 B */

__device__ __forceinline__ uint32_t f2tf32(float x) {
    uint32_t r;
    asm("cvt.rna.tf32.f32 %0, %1;" : "=r"(r) : "f"(x));
    return r;
}
__device__ __forceinline__ float tf32f(float x) {
    return __uint_as_float(f2tf32(x));
}

__device__ __forceinline__ void cp16(float* dst_smem, const float* src) {
    uint32_t d = (uint32_t)__cvta_generic_to_shared(dst_smem);
    asm volatile("cp.async.cg.shared.global [%0], [%1], 16;" :: "r"(d), "l"(src));
}
#define CP_COMMIT() asm volatile("cp.async.commit_group;" ::: "memory")
#define CP_WAIT1()  asm volatile("cp.async.wait_group 1;" ::: "memory")

__device__ __forceinline__ void mma_tf32(float* d, const uint32_t* a,
                                         uint32_t b0, uint32_t b1) {
    asm volatile(
        "mma.sync.aligned.m16n8k8.row.col.f32.tf32.tf32.f32 "
        "{%0,%1,%2,%3}, {%4,%5,%6,%7}, {%8,%9}, {%0,%1,%2,%3};\n"
        : "+f"(d[0]), "+f"(d[1]), "+f"(d[2]), "+f"(d[3])
        : "r"(a[0]), "r"(a[1]), "r"(a[2]), "r"(a[3]), "r"(b0), "r"(b1));
}

__global__ void __launch_bounds__(512) flash_kernel(const float* __restrict__ x,
                                                    float* __restrict__ out) {
    extern __shared__ float sm[];
    float* Qf = sm + SM_QF;
    float* Ks = sm + SM_KS;
    float* Vs = sm + SM_VS;
    float* Ps = sm + SM_PS;
    float* mrow  = sm + SM_MR;
    float* lrow  = sm + SM_LR;
    float* mpart = sm + SM_MP;
    float* spart = sm + SM_SP;

    int qt = blockIdx.x, b = blockIdx.y;
    int n0 = qt * 64;
    const float* qg = g_qkv + (size_t)b * 3 * CC * NPIX;
    const float* kg = qg + (size_t)CC * NPIX;
    const float* vg = kg + (size_t)CC * NPIX;

    int tid  = threadIdx.x;
    int wid  = tid >> 5;
    int lane = tid & 31;
    int g = lane >> 2, t = lane & 3;
    int wr = wid & 3, wc = wid >> 2;
    int m0  = wr * 16;
    int nn0 = wc * 16;
    int d0  = wc * 64;

    /* ---- build fragment-packed Q (one LDS.128 per A-frag later) ----
       Qf[((kb*4 + wr)*32 + lane)*4 + reg], reg order a0,a1,a2,a3 */
    #pragma unroll
    for (int it = 0; it < 8; it++) {
        int idx4 = tid + it * 512;
        int c = idx4 >> 4, i4 = idx4 & 15;
        float4 qv = *(const float4*)(qg + (size_t)c * NPIX + n0 + i4 * 4);
        int kb = c >> 3, cm = c & 7;
        int tt = cm & 3, sel = cm >> 2;
        float v[4] = {qv.x, qv.y, qv.z, qv.w};
        #pragma unroll
        for (int e = 0; e < 4; e++) {
            int i = i4 * 4 + e;
            int wrr = i >> 4, im = i & 15;
            int gq = im & 7, hi = im >> 3;
            Qf[(((kb * 4 + wrr) * 32) + gq * 4 + tt) * 4 + sel * 2 + hi] = v[e];
        }
    }
    if (tid < 64) { mrow[tid] = -INFINITY; lrow[tid] = 0.f; }

    /* prefetch K(0) */
    #pragma unroll
    for (int it = 0; it < 8; it++) {
        int idx4 = tid + it * 512;
        int c = idx4 >> 4, j4 = idx4 & 15;
        cp16(Ks + c * KP + j4 * 4, kg + (size_t)c * NPIX + j4 * 4);
    }
    CP_COMMIT();

    float o[8][4];
    #pragma unroll
    for (int nt = 0; nt < 8; nt++)
        #pragma unroll
        for (int e = 0; e < 4; e++) o[nt][e] = 0.f;

    int r0 = m0 + g, r1 = r0 + 8;

    for (int kt = 0; kt < 64; kt++) {
        int km0 = kt * 64;
        __syncthreads();                       /* A: prev PV done; V buf free */

        /* issue V(kt) — overlaps with S phase */
        #pragma unroll
        for (int it = 0; it < 8; it++) {
            int idx4 = tid + it * 512;
            int c = idx4 >> 4, j4 = idx4 & 15;
            cp16(Vs + c * VPX + j4 * 4, vg + (size_t)c * NPIX + km0 + j4 * 4);
        }
        CP_COMMIT();
        CP_WAIT1();                            /* K(kt) arrived */
        __syncthreads();                       /* B: K visible to all warps */

        /* ---- S = Q^T K via tf32 mma (raw fp32 operands, HW-truncated) ---- */
        float sacc[2][4];
        #pragma unroll
        for (int nt = 0; nt < 2; nt++)
            #pragma unroll
            for (int e = 0; e < 4; e++) sacc[nt][e] = 0.f;

        #pragma unroll 4
        for (int k0 = 0; k0 < 256; k0 += 8) {
            int kb = k0 >> 3;
            float4 aq = *(const float4*)(Qf + ((kb * 4 + wr) * 32 + lane) * 4);
            uint32_t a[4];
            a[0] = __float_as_uint(aq.x);
            a[1] = __float_as_uint(aq.y);
            a[2] = __float_as_uint(aq.z);
            a[3] = __float_as_uint(aq.w);
            #pragma unroll
            for (int nt = 0; nt < 2; nt++) {
                const float* kb_p = Ks + (k0 + t) * KP + nn0 + nt * 8 + g;
                mma_tf32(sacc[nt], a, __float_as_uint(kb_p[0]),
                         __float_as_uint(kb_p[4 * KP]));
            }
        }

        /* ---- rowmax partials ---- */
        float pm0 = fmaxf(fmaxf(sacc[0][0], sacc[0][1]), fmaxf(sacc[1][0], sacc[1][1]));
        float pm1 = fmaxf(fmaxf(sacc[0][2], sacc[0][3]), fmaxf(sacc[1][2], sacc[1][3]));
        pm0 = fmaxf(pm0, __shfl_xor_sync(0xffffffffu, pm0, 1));
        pm0 = fmaxf(pm0, __shfl_xor_sync(0xffffffffu, pm0, 2));
        pm1 = fmaxf(pm1, __shfl_xor_sync(0xffffffffu, pm1, 1));
        pm1 = fmaxf(pm1, __shfl_xor_sync(0xffffffffu, pm1, 2));
        if (t == 0) { mpart[wc * 64 + r0] = pm0; mpart[wc * 64 + r1] = pm1; }
        __syncthreads();                       /* C: maxes ready; K buf free */

        /* issue K(kt+1) — overlaps softmax + PV */
        {
            int kn = (kt + 1 < 64) ? (kt + 1) * 64 : 0;
            #pragma unroll
            for (int it = 0; it < 8; it++) {
                int idx4 = tid + it * 512;
                int c = idx4 >> 4, j4 = idx4 & 15;
                cp16(Ks + c * KP + j4 * 4, kg + (size_t)c * NPIX + kn + j4 * 4);
            }
            CP_COMMIT();
        }

        float mo0 = mrow[r0], mo1 = mrow[r1];
        float mn0 = fmaxf(fmaxf(mo0, fmaxf(mpart[r0], mpart[64 + r0])),
                          fmaxf(mpart[128 + r0], mpart[192 + r0]));
        float mn1 = fmaxf(fmaxf(mo1, fmaxf(mpart[r1], mpart[64 + r1])),
                          fmaxf(mpart[128 + r1], mpart[192 + r1]));
        float alpha0 = __expf(SCALE * (mo0 - mn0));
        float alpha1 = __expf(SCALE * (mo1 - mn1));

        float ps0, ps1;
        {
            int col = nn0 + 2 * t;
            /* truncate p once; sums use truncated values (consistent with PV) */
            float p00 = tf32f(__expf(SCALE * (sacc[0][0] - mn0)));
            float p01 = tf32f(__expf(SCALE * (sacc[0][1] - mn0)));
            float p02 = tf32f(__expf(SCALE * (sacc[0][2] - mn1)));
            float p03 = tf32f(__expf(SCALE * (sacc[0][3] - mn1)));
            float p10 = tf32f(__expf(SCALE * (sacc[1][0] - mn0)));
            float p11 = tf32f(__expf(SCALE * (sacc[1][1] - mn0)));
            float p12 = tf32f(__expf(SCALE * (sacc[1][2] - mn1)));
            float p13 = tf32f(__expf(SCALE * (sacc[1][3] - mn1)));
            *(float2*)(Ps + r0 * PPX + col)     = make_float2(p00, p01);
            *(float2*)(Ps + r1 * PPX + col)     = make_float2(p02, p03);
            *(float2*)(Ps + r0 * PPX + col + 8) = make_float2(p10, p11);
            *(float2*)(Ps + r1 * PPX + col + 8) = make_float2(p12, p13);
            ps0 = p00 + p01 + p10 + p11;
            ps1 = p02 + p03 + p12 + p13;
        }
        ps0 += __shfl_xor_sync(0xffffffffu, ps0, 1);
        ps0 += __shfl_xor_sync(0xffffffffu, ps0, 2);
        ps1 += __shfl_xor_sync(0xffffffffu, ps1, 1);
        ps1 += __shfl_xor_sync(0xffffffffu, ps1, 2);
        if (t == 0) { spart[wc * 64 + r0] = ps0; spart[wc * 64 + r1] = ps1; }

        CP_WAIT1();                            /* V(kt) arrived (K(kt+1) pending) */
        __syncthreads();                       /* D: Ps + sums + V visible */

        if (wid == 0) {
            #pragma unroll
            for (int h = 0; h < 2; h++) {
                int rr = lane + h * 32;
                float mo = mrow[rr];
                float mn = fmaxf(fmaxf(mo, fmaxf(mpart[rr], mpart[64 + rr])),
                                 fmaxf(mpart[128 + rr], mpart[192 + rr]));
                lrow[rr] = lrow[rr] * __expf(SCALE * (mo - mn))
                         + spart[rr] + spart[64 + rr]
                         + spart[128 + rr] + spart[192 + rr];
                mrow[rr] = mn;
            }
        }

        /* ---- O rescale + PV mma ---- */
        #pragma unroll
        for (int nt = 0; nt < 8; nt++) {
            o[nt][0] *= alpha0; o[nt][1] *= alpha0;
            o[nt][2] *= alpha1; o[nt][3] *= alpha1;
        }
        #pragma unroll
        for (int ks = 0; ks < 8; ks++) {
            const float* pa = Ps + r0 * PPX + ks * 8 + t;
            uint32_t ua[4];
            ua[0] = __float_as_uint(pa[0]);
            ua[1] = __float_as_uint(pa[8 * PPX]);
            ua[2] = __float_as_uint(pa[4]);
            ua[3] = __float_as_uint(pa[8 * PPX + 4]);
            #pragma unroll
            for (int nt = 0; nt < 8; nt++) {
                const float* vb = Vs + (d0 + nt * 8 + g) * VPX + ks * 8 + t;
                mma_tf32(o[nt], ua, __float_as_uint(vb[0]),
                         __float_as_uint(vb[4]));
            }
        }
    }

    __syncthreads();
    float il0 = 1.0f / lrow[r0];
    float il1 = 1.0f / lrow[r1];

    /* epilogue: normalize, add ELA, store */
    const float* xg = x + (size_t)b * CC * NPIX;
    float* og = out + (size_t)b * CC * NPIX;
    int i0 = m0 + g, i1 = i0 + 8;     /* w coords; h = qt */
    #pragma unroll
    for (int nt = 0; nt < 8; nt++) {
        #pragma unroll
        for (int bc = 0; bc < 2; bc++) {
            int d = d0 + nt * 8 + 2 * t + bc;
            float xh  = g_s[0][((size_t)b * CC + d) * 64 + qt];
            float xw0 = g_s[1][((size_t)b * CC + d) * 64 + i0];
            float xw1 = g_s[1][((size_t)b * CC + d) * 64 + i1];
            size_t base = (size_t)d * NPIX + n0;
            og[base + i0] = o[nt][bc]     * il0 + xg[base + i0] * xh * xw0;
            og[base + i1] = o[nt][2 + bc] * il1 + xg[base + i1] * xh * xw1;
        }
    }
}

/* ================= launch ================= */
extern "C" void kernel_launch(void* const* d_in, const int* in_sizes, int n_in,
                              void* d_out, int out_size) {
    const float* x     = (const float*)d_in[0];
    const float* wqkv  = (const float*)d_in[1];
    const float* w1    = (const float*)d_in[2];
    const float* b1    = (const float*)d_in[3];
    const float* gamma = (const float*)d_in[4];
    const float* beta  = (const float*)d_in[5];
    float* out = (float*)d_out;

    cudaFuncSetAttribute(gn_kernel, cudaFuncAttributeMaxDynamicSharedMemorySize,
                         (256 * 64 + 512) * 4);
    cudaFuncSetAttribute(flash_kernel, cudaFuncAttributeMaxDynamicSharedMemorySize,
                         ATT_SMEM);

    means_kernel<<<BB * CC, 256>>>(x);
    gn_kernel<<<16, 256, (256 * 64 + 512) * 4>>>(w1, b1, gamma, beta);
    qkv_kernel<<<dim3(12, 64, BB), 256>>>(x, wqkv);
    flash_kernel<<<dim3(64, BB), 512, ATT_SMEM>>>(x, out);
}

// round 8
// speedup vs baseline: 2.9250x; 1.0095x over previous
#include <cuda_runtime.h>
#include <math.h>
#include <stdint.h>

#define BB   8
#define CC   256
#define NPIX 4096
#define NGRP 16
#define SCALE 0.0625f   /* 256^-0.5 */

/* ---- scratch (static device globals: allocation-free) ---- */
__device__ float g_qkv[(size_t)BB * 3 * CC * NPIX];
__device__ float g_y[2][BB * CC * 64];
__device__ float g_s[2][BB * CC * 64];

/* ================= 1. row/col means ================= */
__global__ void __launch_bounds__(256) means_kernel(const float* __restrict__ x) {
    __shared__ float tile[64][65];
    int bc = blockIdx.x;
    const float* xp = x + (size_t)bc * NPIX;
    int tid = threadIdx.x;
    #pragma unroll
    for (int t = 0; t < 16; t++) {
        int idx = tid + t * 256;
        tile[idx >> 6][idx & 63] = xp[idx];
    }
    __syncthreads();
    if (tid < 64) {
        float s = 0.f;
        #pragma unroll
        for (int w = 0; w < 64; w++) s += tile[tid][w];
        g_y[0][(size_t)bc * 64 + tid] = s * (1.0f / 64.0f);
    } else if (tid < 128) {
        int w = tid - 64;
        float s = 0.f;
        #pragma unroll
        for (int h = 0; h < 64; h++) s += tile[h][w];
        g_y[1][(size_t)bc * 64 + w] = s * (1.0f / 64.0f);
    }
}

/* ================= 2. GN + sigmoid branch ================= */
__global__ void __launch_bounds__(256) gn_kernel(const float* __restrict__ w1,
                                                 const float* __restrict__ b1,
                                                 const float* __restrict__ gamma,
                                                 const float* __restrict__ beta) {
    extern __shared__ float sm[];
    float* ys  = sm;
    float* red = sm + 256 * 64;
    __shared__ float mu_s[NGRP], rs_s[NGRP];

    int br = blockIdx.x >> 3;
    int b  = blockIdx.x & 7;
    const float* y = g_y[br] + (size_t)b * CC * 64;
    int tid = threadIdx.x;

    #pragma unroll
    for (int t = 0; t < 16; t++) {
        int i4 = tid + t * 256;
        ((float4*)ys)[i4] = ((const float4*)y)[i4];
    }
    __syncthreads();

    float acc[64];
    #pragma unroll
    for (int l = 0; l < 64; l++) acc[l] = 0.f;

    const float* w1r = w1 + (size_t)tid * CC;
    for (int c = 0; c < CC; c++) {
        float wv = w1r[c];
        const float4* yr = (const float4*)(ys + c * 64);
        #pragma unroll
        for (int l4 = 0; l4 < 16; l4++) {
            float4 yv = yr[l4];
            acc[l4 * 4 + 0] += wv * yv.x;
            acc[l4 * 4 + 1] += wv * yv.y;
            acc[l4 * 4 + 2] += wv * yv.z;
            acc[l4 * 4 + 3] += wv * yv.w;
        }
    }
    float bias = b1[tid];
    float s1 = 0.f, s2 = 0.f;
    #pragma unroll
    for (int l = 0; l < 64; l++) {
        acc[l] += bias;
        s1 += acc[l];
        s2 += acc[l] * acc[l];
    }
    red[tid]       = s1;
    red[256 + tid] = s2;
    __syncthreads();
    if (tid < NGRP) {
        float S = 0.f, S2 = 0.f;
        #pragma unroll
        for (int k = 0; k < 16; k++) {
            S  += red[tid * 16 + k];
            S2 += red[256 + tid * 16 + k];
        }
        float mu  = S * (1.0f / 1024.0f);
        float var = S2 * (1.0f / 1024.0f) - mu * mu;
        mu_s[tid] = mu;
        rs_s[tid] = rsqrtf(var + 1e-5f);
    }
    __syncthreads();
    float mu = mu_s[tid >> 4], rs = rs_s[tid >> 4];
    float ga = gamma[tid], be = beta[tid];
    float* o = g_s[br] + ((size_t)b * CC + tid) * 64;
    #pragma unroll
    for (int l = 0; l < 64; l++) {
        float zn = (acc[l] - mu) * rs;
        float v  = zn * ga + be;
        o[l] = 1.0f / (1.0f + __expf(-v));
    }
}

/* ---- packed fp32x2 helpers (Blackwell dual-fp32 pipe) ---- */
__device__ __forceinline__ uint64_t pack2(float lo, float hi) {
    uint64_t r;
    asm("mov.b64 %0, {%1, %2};" : "=l"(r) : "f"(lo), "f"(hi));
    return r;
}
__device__ __forceinline__ void unpack2(uint64_t v, float& lo, float& hi) {
    asm("mov.b64 {%0, %1}, %2;" : "=f"(lo), "=f"(hi) : "l"(v));
}
__device__ __forceinline__ void fma2(uint64_t& d, uint64_t a, uint64_t b) {
    asm("fma.rn.f32x2 %0, %1, %2, %0;" : "+l"(d) : "l"(a), "l"(b));
}

/* ================= 3. QKV projection (fp32x2 tiled GEMM) ================= */
__global__ void __launch_bounds__(256) qkv_kernel(const float* __restrict__ x,
                                                  const float* __restrict__ wq) {
    __shared__ float a_s[64][33];
    __shared__ float b_s[32][64];
    int mt = blockIdx.x, nt = blockIdx.y, b = blockIdx.z;
    const float* X = x + (size_t)b * CC * NPIX;
    float* outp = g_qkv + (size_t)b * 3 * CC * NPIX;
    int tid = threadIdx.x;
    int tx = tid & 15, ty = tid >> 4;
    int m0 = mt * 64, n0 = nt * 64;
    uint64_t acc2[4][2];
    #pragma unroll
    for (int e = 0; e < 4; e++) { acc2[e][0] = 0ull; acc2[e][1] = 0ull; }

    for (int k0 = 0; k0 < CC; k0 += 32) {
        int cA = tid & 31, rA = tid >> 5;
        #pragma unroll
        for (int i = 0; i < 8; i++)
            a_s[rA + i * 8][cA] = wq[(size_t)(m0 + rA + i * 8) * CC + k0 + cA];
        #pragma unroll
        for (int i = 0; i < 2; i++) {
            int idx4 = tid + i * 256;
            int kk = idx4 >> 4, nn4 = idx4 & 15;
            *(float4*)&b_s[kk][nn4 * 4] =
                *(const float4*)(X + (size_t)(k0 + kk) * NPIX + n0 + nn4 * 4);
        }
        __syncthreads();
        #pragma unroll
        for (int kk = 0; kk < 32; kk++) {
            float4 bv = *(const float4*)&b_s[kk][tx * 4];
            uint64_t b01 = pack2(bv.x, bv.y);
            uint64_t b23 = pack2(bv.z, bv.w);
            #pragma unroll
            for (int e = 0; e < 4; e++) {
                float av = a_s[ty * 4 + e][kk];
                uint64_t a2 = pack2(av, av);
                fma2(acc2[e][0], a2, b01);
                fma2(acc2[e][1], a2, b23);
            }
        }
        __syncthreads();
    }
    #pragma unroll
    for (int e = 0; e < 4; e++) {
        float4 v;
        unpack2(acc2[e][0], v.x, v.y);
        unpack2(acc2[e][1], v.z, v.w);
        *(float4*)(outp + (size_t)(m0 + ty * 4 + e) * NPIX + n0 + tx * 4) = v;
    }
}

/* ================= 4. flash attention (tf32 mma + cp.async pipeline) =======
   grid (64, 8); block 512 = 16 warps, warp grid 4x4.
   - Q pre-packed in fragment order (1 LDS.128 per A-frag)
   - K/V loaded raw via cp.async; HW truncates fp32->tf32 in the MMA
   - P truncated once at Ps write (numerator/denominator consistent)
   - overlap: V(kt) load || S-phase;  K(kt+1) load || softmax+PV */
#define KP  72
#define VPX 68
#define PPX 68
#define QFS (32 * 4 * 32 * 4)            /* 16384 floats, frag-packed Q */
#define SM_QF  0
#define SM_KS  (SM_QF + QFS)
#define SM_VS  (SM_KS + 256 * KP)
#define SM_PS  (SM_VS + 256 * VPX)
#define SM_MR  (SM_PS + 64 * PPX)
#define SM_LR  (SM_MR + 64)
#define SM_MP  (SM_LR + 64)              /* [4][64] */
#define SM_SP  (SM_MP + 256)             /* [4][64] */
#define ATT_SMEM ((SM_SP + 256) * 4)     /* 228,864 B */

__device__ __forceinline__ uint32_t f2tf32(float x) {
    uint32_t r;
    asm("cvt.rna.tf32.f32 %0, %1;" : "=r"(r) : "f"(x));
    return r;
}
__device__ __forceinline__ float tf32f(float x) {
    return __uint_as_float(f2tf32(x));
}

__device__ __forceinline__ void cp16(float* dst_smem, const float* src) {
    uint32_t d = (uint32_t)__cvta_generic_to_shared(dst_smem);
    asm volatile("cp.async.cg.shared.global [%0], [%1], 16;" :: "r"(d), "l"(src));
}
#define CP_COMMIT() asm volatile("cp.async.commit_group;" ::: "memory")
#define CP_WAIT1()  asm volatile("cp.async.wait_group 1;" ::: "memory")

__device__ __forceinline__ void mma_tf32(float* d, const uint32_t* a,
                                         uint32_t b0, uint32_t b1) {
    asm volatile(
        "mma.sync.aligned.m16n8k8.row.col.f32.tf32.tf32.f32 "
        "{%0,%1,%2,%3}, {%4,%5,%6,%7}, {%8,%9}, {%0,%1,%2,%3};\n"
        : "+f"(d[0]), "+f"(d[1]), "+f"(d[2]), "+f"(d[3])
        : "r"(a[0]), "r"(a[1]), "r"(a[2]), "r"(a[3]), "r"(b0), "r"(b1));
}

__global__ void __launch_bounds__(512) flash_kernel(const float* __restrict__ x,
                                                    float* __restrict__ out) {
    extern __shared__ float sm[];
    float* Qf = sm + SM_QF;
    float* Ks = sm + SM_KS;
    float* Vs = sm + SM_VS;
    float* Ps = sm + SM_PS;
    float* mrow  = sm + SM_MR;
    float* lrow  = sm + SM_LR;
    float* mpart = sm + SM_MP;
    float* spart = sm + SM_SP;

    int qt = blockIdx.x, b = blockIdx.y;
    int n0 = qt * 64;
    const float* qg = g_qkv + (size_t)b * 3 * CC * NPIX;
    const float* kg = qg + (size_t)CC * NPIX;
    const float* vg = kg + (size_t)CC * NPIX;

    int tid  = threadIdx.x;
    int wid  = tid >> 5;
    int lane = tid & 31;
    int g = lane >> 2, t = lane & 3;
    int wr = wid & 3, wc = wid >> 2;
    int m0  = wr * 16;
    int nn0 = wc * 16;
    int d0  = wc * 64;

    /* ---- build fragment-packed Q (one LDS.128 per A-frag later) ----
       Qf[((kb*4 + wr)*32 + lane)*4 + reg], reg order a0,a1,a2,a3 */
    #pragma unroll
    for (int it = 0; it < 8; it++) {
        int idx4 = tid + it * 512;
        int c = idx4 >> 4, i4 = idx4 & 15;
        float4 qv = *(const float4*)(qg + (size_t)c * NPIX + n0 + i4 * 4);
        int kb = c >> 3, cm = c & 7;
        int tt = cm & 3, sel = cm >> 2;
        float v[4] = {qv.x, qv.y, qv.z, qv.w};
        #pragma unroll
        for (int e = 0; e < 4; e++) {
            int i = i4 * 4 + e;
            int wrr = i >> 4, im = i & 15;
            int gq = im & 7, hi = im >> 3;
            Qf[(((kb * 4 + wrr) * 32) + gq * 4 + tt) * 4 + sel * 2 + hi] = v[e];
        }
    }
    if (tid < 64) { mrow[tid] = -INFINITY; lrow[tid] = 0.f; }

    /* prefetch K(0) */
    #pragma unroll
    for (int it = 0; it < 8; it++) {
        int idx4 = tid + it * 512;
        int c = idx4 >> 4, j4 = idx4 & 15;
        cp16(Ks + c * KP + j4 * 4, kg + (size_t)c * NPIX + j4 * 4);
    }
    CP_COMMIT();

    float o[8][4];
    #pragma unroll
    for (int nt = 0; nt < 8; nt++)
        #pragma unroll
        for (int e = 0; e < 4; e++) o[nt][e] = 0.f;

    int r0 = m0 + g, r1 = r0 + 8;

    for (int kt = 0; kt < 64; kt++) {
        int km0 = kt * 64;
        __syncthreads();                       /* A: prev PV done; V buf free */

        /* issue V(kt) — overlaps with S phase */
        #pragma unroll
        for (int it = 0; it < 8; it++) {
            int idx4 = tid + it * 512;
            int c = idx4 >> 4, j4 = idx4 & 15;
            cp16(Vs + c * VPX + j4 * 4, vg + (size_t)c * NPIX + km0 + j4 * 4);
        }
        CP_COMMIT();
        CP_WAIT1();                            /* K(kt) arrived */
        __syncthreads();                       /* B: K visible to all warps */

        /* ---- S = Q^T K via tf32 mma (raw fp32 operands, HW-truncated) ---- */
        float sacc[2][4];
        #pragma unroll
        for (int nt = 0; nt < 2; nt++)
            #pragma unroll
            for (int e = 0; e < 4; e++) sacc[nt][e] = 0.f;

        #pragma unroll 8
        for (int k0 = 0; k0 < 256; k0 += 8) {
            int kb = k0 >> 3;
            float4 aq = *(const float4*)(Qf + ((kb * 4 + wr) * 32 + lane) * 4);
            uint32_t a[4];
            a[0] = __float_as_uint(aq.x);
            a[1] = __float_as_uint(aq.y);
            a[2] = __float_as_uint(aq.z);
            a[3] = __float_as_uint(aq.w);
            #pragma unroll
            for (int nt = 0; nt < 2; nt++) {
                const float* kb_p = Ks + (k0 + t) * KP + nn0 + nt * 8 + g;
                mma_tf32(sacc[nt], a, __float_as_uint(kb_p[0]),
                         __float_as_uint(kb_p[4 * KP]));
            }
        }

        /* ---- rowmax partials ---- */
        float pm0 = fmaxf(fmaxf(sacc[0][0], sacc[0][1]), fmaxf(sacc[1][0], sacc[1][1]));
        float pm1 = fmaxf(fmaxf(sacc[0][2], sacc[0][3]), fmaxf(sacc[1][2], sacc[1][3]));
        pm0 = fmaxf(pm0, __shfl_xor_sync(0xffffffffu, pm0, 1));
        pm0 = fmaxf(pm0, __shfl_xor_sync(0xffffffffu, pm0, 2));
        pm1 = fmaxf(pm1, __shfl_xor_sync(0xffffffffu, pm1, 1));
        pm1 = fmaxf(pm1, __shfl_xor_sync(0xffffffffu, pm1, 2));
        if (t == 0) { mpart[wc * 64 + r0] = pm0; mpart[wc * 64 + r1] = pm1; }
        __syncthreads();                       /* C: maxes ready; K buf free */

        /* issue K(kt+1) — overlaps softmax + PV */
        {
            int kn = (kt + 1 < 64) ? (kt + 1) * 64 : 0;
            #pragma unroll
            for (int it = 0; it < 8; it++) {
                int idx4 = tid + it * 512;
                int c = idx4 >> 4, j4 = idx4 & 15;
                cp16(Ks + c * KP + j4 * 4, kg + (size_t)c * NPIX + kn + j4 * 4);
            }
            CP_COMMIT();
        }

        float mo0 = mrow[r0], mo1 = mrow[r1];
        float mn0 = fmaxf(fmaxf(mo0, fmaxf(mpart[r0], mpart[64 + r0])),
                          fmaxf(mpart[128 + r0], mpart[192 + r0]));
        float mn1 = fmaxf(fmaxf(mo1, fmaxf(mpart[r1], mpart[64 + r1])),
                          fmaxf(mpart[128 + r1], mpart[192 + r1]));
        float alpha0 = __expf(SCALE * (mo0 - mn0));
        float alpha1 = __expf(SCALE * (mo1 - mn1));

        float ps0, ps1;
        {
            int col = nn0 + 2 * t;
            /* truncate p once; sums use truncated values (consistent with PV) */
            float p00 = tf32f(__expf(SCALE * (sacc[0][0] - mn0)));
            float p01 = tf32f(__expf(SCALE * (sacc[0][1] - mn0)));
            float p02 = tf32f(__expf(SCALE * (sacc[0][2] - mn1)));
            float p03 = tf32f(__expf(SCALE * (sacc[0][3] - mn1)));
            float p10 = tf32f(__expf(SCALE * (sacc[1][0] - mn0)));
            float p11 = tf32f(__expf(SCALE * (sacc[1][1] - mn0)));
            float p12 = tf32f(__expf(SCALE * (sacc[1][2] - mn1)));
            float p13 = tf32f(__expf(SCALE * (sacc[1][3] - mn1)));
            *(float2*)(Ps + r0 * PPX + col)     = make_float2(p00, p01);
            *(float2*)(Ps + r1 * PPX + col)     = make_float2(p02, p03);
            *(float2*)(Ps + r0 * PPX + col + 8) = make_float2(p10, p11);
            *(float2*)(Ps + r1 * PPX + col + 8) = make_float2(p12, p13);
            ps0 = p00 + p01 + p10 + p11;
            ps1 = p02 + p03 + p12 + p13;
        }
        ps0 += __shfl_xor_sync(0xffffffffu, ps0, 1);
        ps0 += __shfl_xor_sync(0xffffffffu, ps0, 2);
        ps1 += __shfl_xor_sync(0xffffffffu, ps1, 1);
        ps1 += __shfl_xor_sync(0xffffffffu, ps1, 2);
        if (t == 0) { spart[wc * 64 + r0] = ps0; spart[wc * 64 + r1] = ps1; }

        CP_WAIT1();                            /* V(kt) arrived (K(kt+1) pending) */
        __syncthreads();                       /* D: Ps + sums + V visible */

        if (wid == 0) {
            #pragma unroll
            for (int h = 0; h < 2; h++) {
                int rr = lane + h * 32;
                float mo = mrow[rr];
                float mn = fmaxf(fmaxf(mo, fmaxf(mpart[rr], mpart[64 + rr])),
                                 fmaxf(mpart[128 + rr], mpart[192 + rr]));
                lrow[rr] = lrow[rr] * __expf(SCALE * (mo - mn))
                         + spart[rr] + spart[64 + rr]
                         + spart[128 + rr] + spart[192 + rr];
                mrow[rr] = mn;
            }
        }

        /* ---- O rescale + PV mma ---- */
        #pragma unroll
        for (int nt = 0; nt < 8; nt++) {
            o[nt][0] *= alpha0; o[nt][1] *= alpha0;
            o[nt][2] *= alpha1; o[nt][3] *= alpha1;
        }
        #pragma unroll
        for (int ks = 0; ks < 8; ks++) {
            const float* pa = Ps + r0 * PPX + ks * 8 + t;
            uint32_t ua[4];
            ua[0] = __float_as_uint(pa[0]);
            ua[1] = __float_as_uint(pa[8 * PPX]);
            ua[2] = __float_as_uint(pa[4]);
            ua[3] = __float_as_uint(pa[8 * PPX + 4]);
            #pragma unroll
            for (int nt = 0; nt < 8; nt++) {
                const float* vb = Vs + (d0 + nt * 8 + g) * VPX + ks * 8 + t;
                mma_tf32(o[nt], ua, __float_as_uint(vb[0]),
                         __float_as_uint(vb[4]));
            }
        }
    }

    __syncthreads();
    float il0 = 1.0f / lrow[r0];
    float il1 = 1.0f / lrow[r1];

    /* epilogue: normalize, add ELA, store */
    const float* xg = x + (size_t)b * CC * NPIX;
    float* og = out + (size_t)b * CC * NPIX;
    int i0 = m0 + g, i1 = i0 + 8;     /* w coords; h = qt */
    #pragma unroll
    for (int nt = 0; nt < 8; nt++) {
        #pragma unroll
        for (int bc = 0; bc < 2; bc++) {
            int d = d0 + nt * 8 + 2 * t + bc;
            float xh  = g_s[0][((size_t)b * CC + d) * 64 + qt];
            float xw0 = g_s[1][((size_t)b * CC + d) * 64 + i0];
            float xw1 = g_s[1][((size_t)b * CC + d) * 64 + i1];
            size_t base = (size_t)d * NPIX + n0;
            og[base + i0] = o[nt][bc]     * il0 + xg[base + i0] * xh * xw0;
            og[base + i1] = o[nt][2 + bc] * il1 + xg[base + i1] * xh * xw1;
        }
    }
}

/* ================= launch ================= */
extern "C" void kernel_launch(void* const* d_in, const int* in_sizes, int n_in,
                              void* d_out, int out_size) {
    const float* x     = (const float*)d_in[0];
    const float* wqkv  = (const float*)d_in[1];
    const float* w1    = (const float*)d_in[2];
    const float* b1    = (const float*)d_in[3];
    const float* gamma = (const float*)d_in[4];
    const float* beta  = (const float*)d_in[5];
    float* out = (float*)d_out;

    cudaFuncSetAttribute(gn_kernel, cudaFuncAttributeMaxDynamicSharedMemorySize,
                         (256 * 64 + 512) * 4);
    cudaFuncSetAttribute(flash_kernel, cudaFuncAttributeMaxDynamicSharedMemorySize,
                         ATT_SMEM);

    means_kernel<<<BB * CC, 256>>>(x);
    gn_kernel<<<16, 256, (256 * 64 + 512) * 4>>>(w1, b1, gamma, beta);
    qkv_kernel<<<dim3(12, 64, BB), 256>>>(x, wqkv);
    flash_kernel<<<dim3(64, BB), 512, ATT_SMEM>>>(x, out);
}